// round 1
// baseline (speedup 1.0000x reference)
#include <cuda_runtime.h>
#include <math.h>

#define NRAYS 8192
#define SMAX  64
#define NVOX  100000
#define EMB   32
#define HID   128

// scratch: per-point sigma and raw rgb (pre-mask, pre-remap)
__device__ float g_sigma[NRAYS * SMAX];
__device__ float g_rgb[NRAYS * SMAX * 3];

// 128-in -> 128-out dense layer over 32 points.
// thread t owns output column t; in_sh rows have stride 132 floats.
__device__ __forceinline__ void dense128(
    const float* __restrict__ W, const float* __restrict__ b,
    const float* __restrict__ in_sh, float* __restrict__ out_sh,
    bool do_relu, int t)
{
    float acc[32];
    float bj = b[t];
#pragma unroll
    for (int p = 0; p < 32; p++) acc[p] = bj;
#pragma unroll 2
    for (int k = 0; k < 128; k += 4) {
        float w0 = W[(k + 0) * 128 + t];
        float w1 = W[(k + 1) * 128 + t];
        float w2 = W[(k + 2) * 128 + t];
        float w3 = W[(k + 3) * 128 + t];
#pragma unroll
        for (int p = 0; p < 32; p++) {
            float4 v = *(const float4*)(in_sh + p * 132 + k);  // broadcast LDS.128
            float a = acc[p];
            a = fmaf(w0, v.x, a);
            a = fmaf(w1, v.y, a);
            a = fmaf(w2, v.z, a);
            a = fmaf(w3, v.w, a);
            acc[p] = a;
        }
    }
#pragma unroll
    for (int p = 0; p < 32; p++) {
        float x = acc[p];
        out_sh[p * 132 + t] = do_relu ? fmaxf(x, 0.f) : x;
    }
}

__global__ void __launch_bounds__(128, 4)
mlp_kernel(const float* __restrict__ rays_d, const float* __restrict__ pts,
           const int* __restrict__ p2v, const float* __restrict__ vox_emb,
           const float* __restrict__ Wpts, const float* __restrict__ W1,
           const float* __restrict__ b1, const float* __restrict__ W2,
           const float* __restrict__ b2, const float* __restrict__ Wsig,
           const float* __restrict__ bsig, const float* __restrict__ Wfeat,
           const float* __restrict__ bfeat, const float* __restrict__ Wc1,
           const float* __restrict__ bc1, const float* __restrict__ Wc2,
           const float* __restrict__ bc2)
{
    const int ray = blockIdx.x;
    const int t = threadIdx.x;

    __shared__ __align__(16) float ve_sh[32 * 36];   // 32 pts x 32 emb, stride 36
    __shared__ __align__(16) float bufA[32 * 132];
    __shared__ __align__(16) float bufB[32 * 132];
    __shared__ float vemb_sh[27];
    __shared__ float cv_sh[64];                      // view contribution + bc1 per color unit
    __shared__ int   idx_sh[64];
    __shared__ float pts_sh[96];
    __shared__ int   cnt_sh;

    if (t < 64) idx_sh[t] = p2v[ray * 64 + t];
    if (t < 27) {
        float dx = rays_d[ray * 3 + 0];
        float dy = rays_d[ray * 3 + 1];
        float dz = rays_d[ray * 3 + 2];
        float v;
        if (t == 0) v = dx;
        else if (t == 1) v = dy;
        else if (t == 2) v = dz;
        else {
            int u = t - 3;
            bool isc = (u >= 12);
            if (isc) u -= 12;
            int i = u >> 2, l = u & 3;
            float di = (i == 0) ? dx : ((i == 1) ? dy : dz);
            float a = di * (float)(1 << l);
            v = isc ? cosf(a) : sinf(a);
        }
        vemb_sh[t] = v;
    }
    if (t == 0) {
        int c = 0;
        while (c < 64 && p2v[ray * 64 + c] >= 0) c++;  // valid is a prefix by construction
        cnt_sh = c;
    }
    __syncthreads();

    if (t < 64) {
        float s = bc1[t];
#pragma unroll
        for (int k = 0; k < 27; k++) s += Wc1[(128 + k) * 64 + t] * vemb_sh[k];
        cv_sh[t] = s;
    }
    const int cnt = cnt_sh;
    if (cnt == 0) return;  // missed ray: per-ray kernel zero-fills via mask

    for (int chunk = 0; chunk * 32 < cnt; chunk++) {
        const int base = chunk * 32;
        __syncthreads();
        if (t < 96) pts_sh[t] = pts[(ray * 64 + base) * 3 + t];
        __syncthreads();

        // voxel embedding gather + positional lift
        for (int e = t; e < 1024; e += 128) {
            int p = e >> 5, k = e & 31;
            int vid = idx_sh[base + p];
            vid = vid < 0 ? 0 : vid;
            ve_sh[p * 36 + k] = vox_emb[vid * 32 + k]
                + pts_sh[p * 3 + 0] * Wpts[k]
                + pts_sh[p * 3 + 1] * Wpts[32 + k]
                + pts_sh[p * 3 + 2] * Wpts[64 + k];
        }
        __syncthreads();

        // layer 1: 32 -> 128, relu, out -> bufA
        {
            float acc[32];
            float bj = b1[t];
#pragma unroll
            for (int p = 0; p < 32; p++) acc[p] = bj;
#pragma unroll 2
            for (int k = 0; k < 32; k += 4) {
                float w0 = W1[(k + 0) * 128 + t];
                float w1 = W1[(k + 1) * 128 + t];
                float w2 = W1[(k + 2) * 128 + t];
                float w3 = W1[(k + 3) * 128 + t];
#pragma unroll
                for (int p = 0; p < 32; p++) {
                    float4 v = *(const float4*)(ve_sh + p * 36 + k);
                    float a = acc[p];
                    a = fmaf(w0, v.x, a);
                    a = fmaf(w1, v.y, a);
                    a = fmaf(w2, v.z, a);
                    a = fmaf(w3, v.w, a);
                    acc[p] = a;
                }
            }
#pragma unroll
            for (int p = 0; p < 32; p++) bufA[p * 132 + t] = fmaxf(acc[p], 0.f);
        }
        __syncthreads();

        // layer 2: 128 -> 128, relu, bufA -> bufB
        dense128(W2, b2, bufA, bufB, true, t);
        __syncthreads();

        // sigma: 4 threads per point, each sums 32 of 128
        {
            int p = t >> 2, q = t & 3;
            float s = 0.f;
#pragma unroll
            for (int k = q * 32; k < q * 32 + 32; k += 4) {
                float4 h = *(const float4*)(bufB + p * 132 + k);
                float4 w = *(const float4*)(Wsig + k);
                s += h.x * w.x + h.y * w.y + h.z * w.z + h.w * w.w;
            }
            s += __shfl_down_sync(0xffffffffu, s, 1);
            s += __shfl_down_sync(0xffffffffu, s, 2);
            if (q == 0) g_sigma[ray * 64 + base + p] = s + bsig[0];
        }

        // feat: 128 -> 128, no relu, bufB -> bufA (sigma read same bufB, no hazard)
        dense128(Wfeat, bfeat, bufB, bufA, false, t);
        __syncthreads();

        // color layer 1: [feat(128)|vemb(27)] -> 64, relu. View part precomputed in cv_sh.
        // two thread-groups of 64, each covers 16 points; c stored into bufB, stride 68.
        {
            int g = t >> 6, j = t & 63;
            float acc2[16];
            float c0 = cv_sh[j];
#pragma unroll
            for (int i = 0; i < 16; i++) acc2[i] = c0;
#pragma unroll 2
            for (int k = 0; k < 128; k += 4) {
                float w0 = Wc1[(k + 0) * 64 + j];
                float w1 = Wc1[(k + 1) * 64 + j];
                float w2 = Wc1[(k + 2) * 64 + j];
                float w3 = Wc1[(k + 3) * 64 + j];
#pragma unroll
                for (int i = 0; i < 16; i++) {
                    float4 f = *(const float4*)(bufA + (g * 16 + i) * 132 + k);
                    float a = acc2[i];
                    a = fmaf(w0, f.x, a);
                    a = fmaf(w1, f.y, a);
                    a = fmaf(w2, f.z, a);
                    a = fmaf(w3, f.w, a);
                    acc2[i] = a;
                }
            }
#pragma unroll
            for (int i = 0; i < 16; i++) bufB[(g * 16 + i) * 68 + j] = fmaxf(acc2[i], 0.f);
        }
        __syncthreads();

        // rgb: 64 -> 3 (raw, pre-remap)
        if (t < 96) {
            int p = t / 3, ch = t - p * 3;
            float r = bc2[ch];
#pragma unroll 8
            for (int k = 0; k < 64; k++) r += bufB[p * 68 + k] * Wc2[k * 3 + ch];
            g_rgb[(ray * 64 + base) * 3 + t] = r;
        }
    }
}

// per-ray volumetric rendering: warp per ray, 2 samples per lane
__global__ void __launch_bounds__(256)
render_kernel(const float* __restrict__ t_vals, const float* __restrict__ dists,
              const int* __restrict__ p2v, float* __restrict__ out)
{
    int warp = threadIdx.x >> 5;
    int lane = threadIdx.x & 31;
    int ray = blockIdx.x * 8 + warp;
    if (ray >= NRAYS) return;
    int b = ray * 64;
    int i1 = b + lane, i2 = b + 32 + lane;

    bool m1 = p2v[i1] >= 0;
    bool m2 = p2v[i2] >= 0;
    float fe1 = m1 ? fmaxf(g_sigma[i1], 0.f) * dists[i1] : 0.f;
    float fe2 = m2 ? fmaxf(g_sigma[i2], 0.f) * dists[i2] : 0.f;

    // inclusive scans over 64 samples (two 32-wide halves)
    float c1 = fe1;
#pragma unroll
    for (int d = 1; d < 32; d <<= 1) {
        float v = __shfl_up_sync(0xffffffffu, c1, d);
        if (lane >= d) c1 += v;
    }
    float tot = __shfl_sync(0xffffffffu, c1, 31);
    float c2 = fe2;
#pragma unroll
    for (int d = 1; d < 32; d <<= 1) {
        float v = __shfl_up_sync(0xffffffffu, c2, d);
        if (lane >= d) c2 += v;
    }
    c2 += tot;

    float T1 = expf(-(c1 - fe1));
    float T2 = expf(-(c2 - fe2));
    float w1 = (1.f - expf(-fe1)) * T1;
    float w2 = (1.f - expf(-fe2)) * T2;

    float r = 0.f, g = 0.f, bl = 0.f;
    if (m1) {
        float x = g_rgb[i1 * 3 + 0], y = g_rgb[i1 * 3 + 1], z = g_rgb[i1 * 3 + 2];
        r  += w1 * (0.5f * x + 0.5f);
        g  += w1 * (0.5f * y + 0.5f);
        bl += w1 * (0.5f * z + 0.5f);
    }
    if (m2) {
        float x = g_rgb[i2 * 3 + 0], y = g_rgb[i2 * 3 + 1], z = g_rgb[i2 * 3 + 2];
        r  += w2 * (0.5f * x + 0.5f);
        g  += w2 * (0.5f * y + 0.5f);
        bl += w2 * (0.5f * z + 0.5f);
    }
    float aw = w1 + w2;                              // weights are exactly 0 at masked slots
    float dp = w1 * t_vals[i1] + w2 * t_vals[i2];

#pragma unroll
    for (int d = 16; d; d >>= 1) {
        r  += __shfl_down_sync(0xffffffffu, r, d);
        g  += __shfl_down_sync(0xffffffffu, g, d);
        bl += __shfl_down_sync(0xffffffffu, bl, d);
        aw += __shfl_down_sync(0xffffffffu, aw, d);
        dp += __shfl_down_sync(0xffffffffu, dp, d);
    }
    if (lane == 0) {
        bool hit = p2v[b] >= 0;  // counts >= 1, so sample 0 valid iff ray_hits
        float disp = hit ? 1.f / fmaxf(1e-10f, dp / fmaxf(aw, 1e-10f)) : 0.f;
        out[ray * 3 + 0] = hit ? r : 0.f;
        out[ray * 3 + 1] = hit ? g : 0.f;
        out[ray * 3 + 2] = hit ? bl : 0.f;
        out[NRAYS * 3 + ray] = disp;
        out[NRAYS * 4 + ray] = hit ? aw : 0.f;
    }
}

extern "C" void kernel_launch(void* const* d_in, const int* in_sizes, int n_in,
                              void* d_out, int out_size)
{
    const float* rays_d = (const float*)d_in[0];
    const float* pts    = (const float*)d_in[1];
    const float* t_vals = (const float*)d_in[2];
    const float* dists  = (const float*)d_in[3];
    const int* p2v;
    const float *vox, *Wpts, *W1, *b1, *W2, *b2, *Wsig, *bsig, *Wfeat, *bfeat,
                *Wc1, *bc1, *Wc2, *bc2;

    if (in_sizes[4] == NVOX * EMB) {
        // reference-signature order: ..., vox_emb, Wpts, ..., bc2, p2v_idx, ray_hits
        vox   = (const float*)d_in[4];
        Wpts  = (const float*)d_in[5];
        W1    = (const float*)d_in[6];
        b1    = (const float*)d_in[7];
        W2    = (const float*)d_in[8];
        b2    = (const float*)d_in[9];
        Wsig  = (const float*)d_in[10];
        bsig  = (const float*)d_in[11];
        Wfeat = (const float*)d_in[12];
        bfeat = (const float*)d_in[13];
        Wc1   = (const float*)d_in[14];
        bc1   = (const float*)d_in[15];
        Wc2   = (const float*)d_in[16];
        bc2   = (const float*)d_in[17];
        p2v   = (const int*)d_in[18];
    } else {
        // setup_inputs dict order: ..., p2v_idx, ray_hits, vox_emb, Wpts, ...
        p2v   = (const int*)d_in[4];
        vox   = (const float*)d_in[6];
        Wpts  = (const float*)d_in[7];
        W1    = (const float*)d_in[8];
        b1    = (const float*)d_in[9];
        W2    = (const float*)d_in[10];
        b2    = (const float*)d_in[11];
        Wsig  = (const float*)d_in[12];
        bsig  = (const float*)d_in[13];
        Wfeat = (const float*)d_in[14];
        bfeat = (const float*)d_in[15];
        Wc1   = (const float*)d_in[16];
        bc1   = (const float*)d_in[17];
        Wc2   = (const float*)d_in[18];
        bc2   = (const float*)d_in[19];
    }

    mlp_kernel<<<NRAYS, 128>>>(rays_d, pts, p2v, vox, Wpts, W1, b1, W2, b2,
                               Wsig, bsig, Wfeat, bfeat, Wc1, bc1, Wc2, bc2);
    render_kernel<<<NRAYS / 8, 256>>>(t_vals, dists, p2v, (float*)d_out);
}